// round 1
// baseline (speedup 1.0000x reference)
#include <cuda_runtime.h>
#include <math.h>

// Problem constants
#define BSZ   4096
#define DIN   2048
#define HDIM  4096
#define PDIM  256
#define L1DIM 2048
#define PENDIM 2048

// ---------------- scratch (device globals; no allocations allowed) ----------
__device__ float d_hidden[BSZ * HDIM];            // 64 MB
__device__ float d_act[BSZ * HDIM];               // 64 MB
__device__ float d_logit[BSZ * PDIM];             // 4 MB (reused for both argmax stages)
__device__ float d_Mcur[PDIM * L1DIM];
__device__ float d_L1mat[PDIM * PDIM];
__device__ float d_NL1[PDIM * PDIM];
__device__ float d_PEN0[PDIM * PENDIM];
__device__ float d_PEN1[PDIM * PENDIM];
__device__ float d_D0[PDIM * PDIM];
__device__ float d_D1[PDIM * PDIM];
__device__ int   d_i0[BSZ], d_i1[BSZ], d_ni0[BSZ], d_ni1[BSZ];
__device__ float d_pe[BSZ], d_conf[BSZ], d_prod[BSZ];
__device__ float d_scal[2];   // [0] = mean(pe), [1] = routing_cost

// ---------------- generic fp32 tiled GEMM -----------------------------------
// C[M,N] = A[M,K] @ B[K,N]  (+bias per column if EPI>=1, relu if EPI==2)
// All dims must be divisible by tile sizes (true for every call below).
template<int BM, int BN, int BK, int TM, int TN, int EPI>
__global__ void sgemm_kernel(int M, int N, int K,
                             const float* __restrict__ A, int lda,
                             const float* __restrict__ B, int ldb,
                             const float* __restrict__ bias,
                             float* __restrict__ C, int ldc)
{
    constexpr int THREADS = (BM / TM) * (BN / TN);
    __shared__ float As[BK][BM];
    __shared__ float Bs[BK][BN];

    const int tid = threadIdx.x;
    const int tx  = tid % (BN / TN);
    const int ty  = tid / (BN / TN);
    const int m0  = blockIdx.y * BM;
    const int n0  = blockIdx.x * BN;

    float acc[TM][TN];
#pragma unroll
    for (int i = 0; i < TM; i++)
#pragma unroll
        for (int j = 0; j < TN; j++) acc[i][j] = 0.0f;

    constexpr int A_VEC = (BM * BK) / (4 * THREADS);   // float4 loads per thread
    constexpr int B_VEC = (BK * BN) / (4 * THREADS);
    static_assert(A_VEC >= 1 && B_VEC >= 1, "tile too small");

    for (int k0 = 0; k0 < K; k0 += BK) {
        // A tile -> As[k][m] (transposed store for coalesced compute reads)
#pragma unroll
        for (int i = 0; i < A_VEC; i++) {
            int idx  = tid + i * THREADS;          // float4 index within BM x BK tile
            int row  = idx / (BK / 4);
            int col4 = idx % (BK / 4);
            float4 v = *reinterpret_cast<const float4*>(&A[(size_t)(m0 + row) * lda + k0 + col4 * 4]);
            As[col4 * 4 + 0][row] = v.x;
            As[col4 * 4 + 1][row] = v.y;
            As[col4 * 4 + 2][row] = v.z;
            As[col4 * 4 + 3][row] = v.w;
        }
        // B tile -> Bs[k][n]
#pragma unroll
        for (int i = 0; i < B_VEC; i++) {
            int idx  = tid + i * THREADS;
            int row  = idx / (BN / 4);
            int col4 = idx % (BN / 4);
            float4 v = *reinterpret_cast<const float4*>(&B[(size_t)(k0 + row) * ldb + n0 + col4 * 4]);
            *reinterpret_cast<float4*>(&Bs[row][col4 * 4]) = v;
        }
        __syncthreads();

#pragma unroll
        for (int k = 0; k < BK; k++) {
            float af[TM], bf[TN];
#pragma unroll
            for (int i = 0; i < TM; i++) af[i] = As[k][ty * TM + i];
#pragma unroll
            for (int j = 0; j < TN; j++) bf[j] = Bs[k][tx * TN + j];
#pragma unroll
            for (int i = 0; i < TM; i++)
#pragma unroll
                for (int j = 0; j < TN; j++)
                    acc[i][j] = fmaf(af[i], bf[j], acc[i][j]);
        }
        __syncthreads();
    }

#pragma unroll
    for (int i = 0; i < TM; i++) {
        int m = m0 + ty * TM + i;
#pragma unroll
        for (int j = 0; j < TN; j++) {
            int n = n0 + tx * TN + j;
            float v = acc[i][j];
            if (EPI >= 1) v += bias[n];
            if (EPI == 2) v = fmaxf(v, 0.0f);
            C[(size_t)m * ldc + n] = v;
        }
    }
}

// ---------------- argmax over P=256 per batch row ----------------------------
// out[r] = argmax_t ( mat[row(r)*256 + t] + g[r*256 + t] ), first-index on ties
__global__ void argmax_kernel(const float* __restrict__ mat,
                              const float* __restrict__ g,
                              const int* __restrict__ rowIdx, int useIdx,
                              int* __restrict__ out)
{
    int r = blockIdx.x;
    int t = threadIdx.x;                 // 256 threads
    int row = useIdx ? rowIdx[r] : r;
    float v = mat[row * PDIM + t] + g[(size_t)r * PDIM + t];

    __shared__ float sv[256];
    __shared__ int   si[256];
    sv[t] = v; si[t] = t;
    __syncthreads();
#pragma unroll
    for (int s = 128; s > 0; s >>= 1) {
        if (t < s) {
            float v2 = sv[t + s]; int i2 = si[t + s];
            if (v2 > sv[t] || (v2 == sv[t] && i2 < si[t])) { sv[t] = v2; si[t] = i2; }
        }
        __syncthreads();
    }
    if (t == 0) out[r] = si[0];
}

// ---------------- pairwise squared-distance tables ---------------------------
// D[p,q] = sum_{j<2048} (A[p, aoff+j] - Bm[q, j])^2 ; grid (16,16), 256 thr
__global__ void dist_kernel(const float* __restrict__ A, int lda, int aoff,
                            const float* __restrict__ Bm, int ldb,
                            float* __restrict__ D)
{
    __shared__ float As[16][33];
    __shared__ float Bs[16][33];
    int tx = threadIdx.x % 16;  // q
    int ty = threadIdx.x / 16;  // p
    int p0 = blockIdx.y * 16, q0 = blockIdx.x * 16;
    float acc = 0.0f;

    for (int k0 = 0; k0 < 2048; k0 += 32) {
        int row = threadIdx.x / 16;
        int col = (threadIdx.x % 16) * 2;
        float2 va = *reinterpret_cast<const float2*>(&A[(size_t)(p0 + row) * lda + aoff + k0 + col]);
        As[row][col] = va.x; As[row][col + 1] = va.y;
        float2 vb = *reinterpret_cast<const float2*>(&Bm[(size_t)(q0 + row) * ldb + k0 + col]);
        Bs[row][col] = vb.x; Bs[row][col + 1] = vb.y;
        __syncthreads();
#pragma unroll
        for (int k = 0; k < 32; k++) {
            float d = As[ty][k] - Bs[tx][k];
            acc = fmaf(d, d, acc);
        }
        __syncthreads();
    }
    D[(p0 + ty) * PDIM + q0 + tx] = acc;
}

// ---------------- scalar chain ----------------------------------------------
__global__ void pe_kernel()
{
    int b = blockIdx.x * blockDim.x + threadIdx.x;
    int i0 = d_i0[b], ni0 = d_ni0[b], ni1 = d_ni1[b];
    d_pe[b] = (d_D0[i0 * PDIM + ni0] + d_D1[i0 * PDIM + ni1]) * (1.0f / 4096.0f);
}

__global__ void mean_kernel()   // 1 block, 1024 threads: mean(pe) -> d_scal[0]
{
    __shared__ float s[1024];
    int t = threadIdx.x;
    float v = 0.0f;
    for (int i = t; i < BSZ; i += 1024) v += d_pe[i];
    s[t] = v; __syncthreads();
    for (int st = 512; st > 0; st >>= 1) { if (t < st) s[t] += s[t + st]; __syncthreads(); }
    if (t == 0) d_scal[0] = s[0] * (1.0f / 4096.0f);
}

__global__ void conf_kernel()
{
    int b = blockIdx.x * blockDim.x + threadIdx.x;
    float pe   = d_pe[b];
    float pc   = fabsf(pe - d_scal[0]);
    float temp = 1.0f / (1.0f + expf(-pc));           // sigmoid
    float conf = 0.5f * (tanhf(-pe * temp) + 1.0f);
    d_conf[b] = conf;
    d_prod[b] = conf * (1.0f - conf);
}

__global__ void rc_kernel()     // 1 block: routing_cost -> d_scal[1]
{
    __shared__ float s[1024];
    int t = threadIdx.x;
    float v = 0.0f;
    for (int i = t; i < BSZ; i += 1024) v += d_prod[i];
    s[t] = v; __syncthreads();
    for (int st = 512; st > 0; st >>= 1) { if (t < st) s[t] += s[t + st]; __syncthreads(); }
    if (t == 0) d_scal[1] = 0.1f * (s[0] * (1.0f / 4096.0f));
}

// ---------------- output kernels --------------------------------------------
__global__ void contup_kernel(float* __restrict__ out)   // [4096,4096]
{
    int i = blockIdx.x * blockDim.x + threadIdx.x;       // float4 idx; 4096 floats/row = 1024 f4
    float4 h = reinterpret_cast<const float4*>(d_hidden)[i];
    float s = 1.0f - d_conf[i >> 10];
    h.x *= s; h.y *= s; h.z *= s; h.w *= s;
    reinterpret_cast<float4*>(out)[i] = h;
}

__global__ void penult_kernel(float* __restrict__ out)   // [4096,2048]
{
    int i = blockIdx.x * blockDim.x + threadIdx.x;       // float4 idx; 512 f4 per row
    int b = i >> 9;
    int j = i & 511;
    float4 p0 = reinterpret_cast<const float4*>(d_PEN0)[d_i0[b] * 512 + j];
    float4 p1 = reinterpret_cast<const float4*>(d_PEN1)[d_i1[b] * 512 + j];
    float c = d_conf[b];
    float4 o;
    o.x = (p0.x + p1.x) * c;
    o.y = (p0.y + p1.y) * c;
    o.z = (p0.z + p1.z) * c;
    o.w = (p0.w + p1.w) * c;
    reinterpret_cast<float4*>(out)[i] = o;
}

__global__ void peout_kernel(float* __restrict__ out)    // [4096,1]
{
    int b = blockIdx.x * blockDim.x + threadIdx.x;
    out[b] = d_pe[b] + d_scal[1];
}

// ---------------- launch -----------------------------------------------------
extern "C" void kernel_launch(void* const* d_in, const int* in_sizes, int n_in,
                              void* d_out, int out_size)
{
    const float* x         = (const float*)d_in[0];
    const float* g_main0   = (const float*)d_in[1];
    const float* g_main1   = (const float*)d_in[2];
    const float* g_next0   = (const float*)d_in[3];
    const float* g_next1   = (const float*)d_in[4];
    const float* W_proc    = (const float*)d_in[5];
    const float* b_proc    = (const float*)d_in[6];
    const float* patterns0 = (const float*)d_in[7];
    const float* patterns1 = (const float*)d_in[8];
    const float* attn0_W   = (const float*)d_in[9];
    const float* attn0_b   = (const float*)d_in[10];
    const float* attn1_W   = (const float*)d_in[11];
    const float* attn1_b   = (const float*)d_in[12];
    const float* proj0_W   = (const float*)d_in[13];
    const float* proj0_b   = (const float*)d_in[14];
    const float* pen_W     = (const float*)d_in[15];
    const float* pen_b     = (const float*)d_in[16];
    const float* nW_proc   = (const float*)d_in[17];
    const float* nb_proc   = (const float*)d_in[18];
    const float* npat0     = (const float*)d_in[19];
    const float* npat1     = (const float*)d_in[20];
    const float* nattn0_W  = (const float*)d_in[21];
    const float* nattn0_b  = (const float*)d_in[22];
    const float* nattn1_W  = (const float*)d_in[23];
    const float* nattn1_b  = (const float*)d_in[24];

    float *hidden, *act, *logit, *Mcur, *L1mat, *NL1, *PEN0, *PEN1, *D0, *D1;
    int *i0p, *i1p, *ni0p, *ni1p;
    cudaGetSymbolAddress((void**)&hidden, d_hidden);
    cudaGetSymbolAddress((void**)&act,    d_act);
    cudaGetSymbolAddress((void**)&logit,  d_logit);
    cudaGetSymbolAddress((void**)&Mcur,   d_Mcur);
    cudaGetSymbolAddress((void**)&L1mat,  d_L1mat);
    cudaGetSymbolAddress((void**)&NL1,    d_NL1);
    cudaGetSymbolAddress((void**)&PEN0,   d_PEN0);
    cudaGetSymbolAddress((void**)&PEN1,   d_PEN1);
    cudaGetSymbolAddress((void**)&D0,     d_D0);
    cudaGetSymbolAddress((void**)&D1,     d_D1);
    cudaGetSymbolAddress((void**)&i0p,    d_i0);
    cudaGetSymbolAddress((void**)&i1p,    d_i1);
    cudaGetSymbolAddress((void**)&ni0p,   d_ni0);
    cudaGetSymbolAddress((void**)&ni1p,   d_ni1);

    float* out = (float*)d_out;
    float* out_cont = out;                                   // 4096*4096
    float* out_pen  = out + (size_t)BSZ * HDIM;              // 4096*2048
    float* out_pe   = out + (size_t)BSZ * HDIM + (size_t)BSZ * PENDIM;

    // ---- pattern-space precomputes (batch independent, tiny) ----
    // Mcur = patterns0 @ proj0_W + proj0_b             [256,2048] K=4096
    sgemm_kernel<64,64,16,4,4,1><<<dim3(L1DIM/64, PDIM/64), 256>>>(
        PDIM, L1DIM, HDIM, patterns0, HDIM, proj0_W, L1DIM, proj0_b, Mcur, L1DIM);
    // L1mat = Mcur @ attn1_W + attn1_b                 [256,256] K=2048
    sgemm_kernel<64,64,16,4,4,1><<<dim3(PDIM/64, PDIM/64), 256>>>(
        PDIM, PDIM, L1DIM, Mcur, L1DIM, attn1_W, PDIM, attn1_b, L1mat, PDIM);
    // NL1 = npatterns0 @ nattn1_W + nattn1_b           [256,256] K=2048
    sgemm_kernel<64,64,16,4,4,1><<<dim3(PDIM/64, PDIM/64), 256>>>(
        PDIM, PDIM, L1DIM, npat0, L1DIM, nattn1_W, PDIM, nattn1_b, NL1, PDIM);
    // PEN0 = patterns0 @ pen_W[0:4096,:]               [256,2048] K=4096 (no bias)
    sgemm_kernel<64,64,16,4,4,0><<<dim3(PENDIM/64, PDIM/64), 256>>>(
        PDIM, PENDIM, HDIM, patterns0, HDIM, pen_W, PENDIM, (const float*)0, PEN0, PENDIM);
    // PEN1 = patterns1 @ pen_W[4096:6144,:] + pen_b    [256,2048] K=2048
    sgemm_kernel<64,64,16,4,4,1><<<dim3(PENDIM/64, PDIM/64), 256>>>(
        PDIM, PENDIM, L1DIM, patterns1, L1DIM, pen_W + (size_t)HDIM * PENDIM, PENDIM,
        pen_b, PEN1, PENDIM);
    // D0[p,q] = ||patterns0[p,0:2048] - npat0[q]||^2
    dist_kernel<<<dim3(16,16), 256>>>(patterns0, HDIM, 0,    npat0, L1DIM, D0);
    // D1[p,q] = ||patterns0[p,2048:4096] - npat1[q]||^2
    dist_kernel<<<dim3(16,16), 256>>>(patterns0, HDIM, 2048, npat1, L1DIM, D1);

    // ---- big batch GEMMs ----
    // hidden = relu(x @ W_proc + b_proc)               [4096,4096] K=2048
    sgemm_kernel<128,128,16,8,8,2><<<dim3(HDIM/128, BSZ/128), 256>>>(
        BSZ, HDIM, DIN, x, DIN, W_proc, HDIM, b_proc, hidden, HDIM);
    // logit = hidden @ attn0_W + attn0_b               [4096,256] K=4096
    sgemm_kernel<64,64,16,4,4,1><<<dim3(PDIM/64, BSZ/64), 256>>>(
        BSZ, PDIM, HDIM, hidden, HDIM, attn0_W, PDIM, attn0_b, logit, PDIM);
    argmax_kernel<<<BSZ, 256>>>(logit, g_main0, (const int*)0, 0, i0p);

    // act = relu(hidden @ nW_proc + nb_proc)           [4096,4096] K=4096
    sgemm_kernel<128,128,16,8,8,2><<<dim3(HDIM/128, BSZ/128), 256>>>(
        BSZ, HDIM, HDIM, hidden, HDIM, nW_proc, HDIM, nb_proc, act, HDIM);
    // logit = act @ nattn0_W + nattn0_b                [4096,256] K=4096
    sgemm_kernel<64,64,16,4,4,1><<<dim3(PDIM/64, BSZ/64), 256>>>(
        BSZ, PDIM, HDIM, act, HDIM, nattn0_W, PDIM, nattn0_b, logit, PDIM);
    argmax_kernel<<<BSZ, 256>>>(logit, g_next0, (const int*)0, 0, ni0p);

    // ---- second-stage argmaxes via table gathers ----
    argmax_kernel<<<BSZ, 256>>>(L1mat, g_main1, i0p, 1, i1p);
    argmax_kernel<<<BSZ, 256>>>(NL1,   g_next1, ni0p, 1, ni1p);

    // ---- scalar chain ----
    pe_kernel  <<<BSZ/256, 256>>>();
    mean_kernel<<<1, 1024>>>();
    conf_kernel<<<BSZ/256, 256>>>();
    rc_kernel  <<<1, 1024>>>();

    // ---- outputs ----
    contup_kernel<<<(BSZ*HDIM/4)/256, 256>>>(out_cont);
    penult_kernel<<<(BSZ*PENDIM/4)/256, 256>>>(out_pen);
    peout_kernel <<<BSZ/256, 256>>>(out_pe);

    (void)in_sizes; (void)n_in; (void)out_size;
}

// round 3
// speedup vs baseline: 1.1769x; 1.1769x over previous
#include <cuda_runtime.h>
#include <cuda_bf16.h>
#include <math.h>
#include <stdint.h>

// Problem constants
#define BSZ   4096
#define DIN   2048
#define HDIM  4096
#define PDIM  256
#define L1DIM 2048
#define PENDIM 2048

// ===================== device scratch (no allocations allowed) ===============
__device__ float d_hidden[BSZ * HDIM];
__device__ float d_act[BSZ * HDIM];
__device__ float d_logit[BSZ * PDIM];
__device__ float d_Mcur[PDIM * L1DIM];
__device__ float d_L1mat[PDIM * PDIM];
__device__ float d_NL1[PDIM * PDIM];
__device__ float d_PEN0[PDIM * PENDIM];
__device__ float d_PEN1[PDIM * PENDIM];
__device__ float d_D0[PDIM * PDIM];
__device__ float d_D1[PDIM * PDIM];
__device__ int   d_i0[BSZ], d_i1[BSZ], d_ni0[BSZ], d_ni1[BSZ];
__device__ float d_pe[BSZ], d_conf[BSZ], d_prod[BSZ];
__device__ float d_scal[2];

// transposed + 3-way-split bf16 weights: layout [3][N][K]
__device__ __nv_bfloat16 bt_wproc [3ull * 4096 * 2048];
__device__ __nv_bfloat16 bt_nwproc[3ull * 4096 * 4096];
__device__ __nv_bfloat16 bt_attn0 [3ull * 256  * 4096];
__device__ __nv_bfloat16 bt_nattn0[3ull * 256  * 4096];
__device__ __nv_bfloat16 bt_proj0 [3ull * 2048 * 4096];
__device__ __nv_bfloat16 bt_attn1 [3ull * 256  * 2048];
__device__ __nv_bfloat16 bt_nattn1[3ull * 256  * 2048];
__device__ __nv_bfloat16 bt_pen   [3ull * 2048 * 6144];

// ===================== helpers ===============================================
__device__ __forceinline__ uint32_t smem_u32(const void* p) {
    uint32_t a;
    asm("{ .reg .u64 t; cvta.to.shared.u64 t, %1; cvt.u32.u64 %0, t; }" : "=r"(a) : "l"(p));
    return a;
}

__device__ __forceinline__ void ldsm4(uint32_t& r0, uint32_t& r1, uint32_t& r2,
                                      uint32_t& r3, uint32_t addr) {
    asm volatile("ldmatrix.sync.aligned.m8n8.x4.shared.b16 {%0,%1,%2,%3}, [%4];"
                 : "=r"(r0), "=r"(r1), "=r"(r2), "=r"(r3) : "r"(addr));
}

__device__ __forceinline__ void mma16816(float* c, const uint32_t* a, const uint32_t* b) {
    asm volatile("mma.sync.aligned.m16n8k16.row.col.f32.bf16.bf16.f32 "
                 "{%0,%1,%2,%3}, {%4,%5,%6,%7}, {%8,%9}, {%0,%1,%2,%3};"
                 : "+f"(c[0]), "+f"(c[1]), "+f"(c[2]), "+f"(c[3])
                 : "r"(a[0]), "r"(a[1]), "r"(a[2]), "r"(a[3]), "r"(b[0]), "r"(b[1]));
}

__device__ __forceinline__ void split3(float a, __nv_bfloat16& b0, __nv_bfloat16& b1,
                                       __nv_bfloat16& b2) {
    b0 = __float2bfloat16(a);
    float r = a - __bfloat162float(b0);
    b1 = __float2bfloat16(r);
    float r2 = r - __bfloat162float(b1);
    b2 = __float2bfloat16(r2);
}

// ===================== split-bf16 mma.sync GEMM ==============================
// C[M,N] = A[M,K](fp32,K-major) @ Bt[N,K](bf16 x3 planes)
// EPI: 0 none, 1 +bias, 2 +bias+relu
// SMEM: per stage: A 3 planes [128][40]bf16 + B 3 planes [128][40]bf16
static constexpr int PLANE_B = 128 * 40 * 2;          // 10240 bytes per plane
static constexpr int STAGE_B = 6 * PLANE_B;           // 61440
static constexpr int SMEM_GEMM = 2 * STAGE_B;         // 122880

template<int EPI>
__global__ void __launch_bounds__(256, 1)
mma_gemm(int M, int N, int K,
         const float* __restrict__ A, int lda,
         const __nv_bfloat16* __restrict__ Bt, int ldb, size_t planeB,
         const float* __restrict__ bias,
         float* __restrict__ C, int ldc)
{
    extern __shared__ char smem[];
    const uint32_t sb = smem_u32(smem);
    const int tid = threadIdx.x;
    const int lane = tid & 31;
    const int w = tid >> 5;
    const int wm = w & 1;          // 2 m-blocks of 64
    const int wn = w >> 1;         // 4 n-blocks of 32

    // block swizzle for L2 locality
    const int nbm = M >> 7, nbn = N >> 7;
    int bid = blockIdx.x;
    const int GRP = 8;
    int per = GRP * nbn;
    int g = bid / per, r = bid % per;
    int gm = nbm - g * GRP; if (gm > GRP) gm = GRP;
    const int mb = g * GRP + (r % gm);
    const int nb = r / gm;
    const int m0 = mb * 128, n0 = nb * 128;

    // per-thread ldmatrix lane-address components
    const int seg = lane >> 3, rr = lane & 7;
    const int a_row = (seg & 1) * 8 + rr, a_col = (seg >> 1) * 8;
    const int b_row = (seg >> 1) * 8 + rr, b_col = (seg & 1) * 8;

    float acc[4][4][4];
#pragma unroll
    for (int i = 0; i < 4; i++)
#pragma unroll
        for (int j = 0; j < 4; j++)
#pragma unroll
            for (int e = 0; e < 4; e++) acc[i][j][e] = 0.0f;

    const int S = K >> 5;          // BK = 32
    float4 av[4];
    uint4  bv[6];

    // ---- gmem load helpers (manually inlined per stage) ----
    // A: 128x32 fp32 -> 4 float4/thread ; B: 3 planes x 128x32 bf16 -> 6 uint4/thread
    // prologue: load + store stage 0
    {
        const int kb = 0;
#pragma unroll
        for (int i = 0; i < 4; i++) {
            int idx = tid + i * 256;
            int row = idx >> 3, c4 = idx & 7;
            av[i] = *reinterpret_cast<const float4*>(&A[(size_t)(m0 + row) * lda + kb + c4 * 4]);
        }
#pragma unroll
        for (int i = 0; i < 6; i++) {
            int idx = tid + i * 256;
            int pl = idx >> 9, rem = idx & 511;
            int row = rem >> 2, gg = rem & 3;
            bv[i] = *reinterpret_cast<const uint4*>(
                &Bt[(size_t)pl * planeB + (size_t)(n0 + row) * ldb + kb + gg * 8]);
        }
    }

    for (int s = 0; s < S; s++) {
        const int buf = s & 1;
        // ---- store staged regs into smem buf ----
        {
            char* abase = smem + buf * STAGE_B;
            char* bbase = abase + 3 * PLANE_B;
#pragma unroll
            for (int i = 0; i < 4; i++) {
                int idx = tid + i * 256;
                int row = idx >> 3, c4 = idx & 7;
                uint32_t off = row * 80 + c4 * 8;       // bytes
                float f[4] = { av[i].x, av[i].y, av[i].z, av[i].w };
                __nv_bfloat16 q[3][4];
#pragma unroll
                for (int e = 0; e < 4; e++) split3(f[e], q[0][e], q[1][e], q[2][e]);
#pragma unroll
                for (int t = 0; t < 3; t++) {
                    __nv_bfloat162 p0; p0.x = q[t][0]; p0.y = q[t][1];
                    __nv_bfloat162 p1; p1.x = q[t][2]; p1.y = q[t][3];
                    *reinterpret_cast<__nv_bfloat162*>(abase + t * PLANE_B + off) = p0;
                    *reinterpret_cast<__nv_bfloat162*>(abase + t * PLANE_B + off + 4) = p1;
                }
            }
#pragma unroll
            for (int i = 0; i < 6; i++) {
                int idx = tid + i * 256;
                int pl = idx >> 9, rem = idx & 511;
                int row = rem >> 2, gg = rem & 3;
                *reinterpret_cast<uint4*>(bbase + pl * PLANE_B + row * 80 + gg * 16) = bv[i];
            }
        }
        __syncthreads();

        // ---- prefetch next stage gmem -> regs ----
        if (s + 1 < S) {
            const int kb = (s + 1) << 5;
#pragma unroll
            for (int i = 0; i < 4; i++) {
                int idx = tid + i * 256;
                int row = idx >> 3, c4 = idx & 7;
                av[i] = *reinterpret_cast<const float4*>(&A[(size_t)(m0 + row) * lda + kb + c4 * 4]);
            }
#pragma unroll
            for (int i = 0; i < 6; i++) {
                int idx = tid + i * 256;
                int pl = idx >> 9, rem = idx & 511;
                int row = rem >> 2, gg = rem & 3;
                bv[i] = *reinterpret_cast<const uint4*>(
                    &Bt[(size_t)pl * planeB + (size_t)(n0 + row) * ldb + kb + gg * 8]);
            }
        }

        // ---- compute on buf ----
        {
            const uint32_t abase = sb + buf * STAGE_B;
            const uint32_t bbase = abase + 3 * PLANE_B;
#pragma unroll
            for (int k16 = 0; k16 < 2; k16++) {
                uint32_t afr[3][4][4];
#pragma unroll
                for (int p = 0; p < 3; p++) {
#pragma unroll
                    for (int i = 0; i < 4; i++) {
                        uint32_t addr = abase + p * PLANE_B
                            + (uint32_t)(wm * 64 + i * 16 + a_row) * 80
                            + (uint32_t)(k16 * 16 + a_col) * 2;
                        ldsm4(afr[p][i][0], afr[p][i][1], afr[p][i][2], afr[p][i][3], addr);
                    }
                }
#pragma unroll
                for (int bp = 0; bp < 3; bp++) {
                    uint32_t bfr[4][2];
#pragma unroll
                    for (int jp = 0; jp < 2; jp++) {
                        uint32_t addr = bbase + bp * PLANE_B
                            + (uint32_t)(wn * 32 + jp * 16 + b_row) * 80
                            + (uint32_t)(k16 * 16 + b_col) * 2;
                        ldsm4(bfr[2*jp][0], bfr[2*jp][1], bfr[2*jp+1][0], bfr[2*jp+1][1], addr);
                    }
                    const int napl = (bp == 0) ? 3 : (bp == 1 ? 2 : 1);
#pragma unroll
                    for (int ap = 0; ap < 3; ap++) {
                        if (ap < napl) {
#pragma unroll
                            for (int i = 0; i < 4; i++)
#pragma unroll
                                for (int j = 0; j < 4; j++)
                                    mma16816(acc[i][j], afr[ap][i], bfr[j]);
                        }
                    }
                }
            }
        }
        __syncthreads();
    }

    // ---- epilogue ----
#pragma unroll
    for (int i = 0; i < 4; i++) {
        int row0 = m0 + wm * 64 + i * 16 + (lane >> 2);
#pragma unroll
        for (int j = 0; j < 4; j++) {
            int col = n0 + wn * 32 + j * 8 + 2 * (lane & 3);
            float b0 = 0.f, b1 = 0.f;
            if (EPI >= 1) { b0 = bias[col]; b1 = bias[col + 1]; }
            float2 v0, v1;
            v0.x = acc[i][j][0] + b0; v0.y = acc[i][j][1] + b1;
            v1.x = acc[i][j][2] + b0; v1.y = acc[i][j][3] + b1;
            if (EPI == 2) {
                v0.x = fmaxf(v0.x, 0.f); v0.y = fmaxf(v0.y, 0.f);
                v1.x = fmaxf(v1.x, 0.f); v1.y = fmaxf(v1.y, 0.f);
            }
            *reinterpret_cast<float2*>(&C[(size_t)row0 * ldc + col]) = v0;
            *reinterpret_cast<float2*>(&C[(size_t)(row0 + 8) * ldc + col]) = v1;
        }
    }
}

// ===================== transpose + 3-way split: in[K,N]fp32 -> out[3][N,K]bf16
__global__ void tsplit_kernel(const float* __restrict__ in, int K, int N,
                              __nv_bfloat16* __restrict__ out, size_t plane)
{
    __shared__ float t[32][33];
    int n0 = blockIdx.x * 32, k0 = blockIdx.y * 32;
    int tx = threadIdx.x & 31, ty = threadIdx.x >> 5;   // 256 thr: ty 0..7
#pragma unroll
    for (int r = 0; r < 4; r++)
        t[ty + 8 * r][tx] = in[(size_t)(k0 + ty + 8 * r) * N + n0 + tx];
    __syncthreads();
#pragma unroll
    for (int r = 0; r < 4; r++) {
        float v = t[tx][ty + 8 * r];            // = in[k0+tx][n0+ty+8r]
        __nv_bfloat16 b0, b1, b2;
        split3(v, b0, b1, b2);
        size_t o = (size_t)(n0 + ty + 8 * r) * K + k0 + tx;
        out[o] = b0;
        out[plane + o] = b1;
        out[2 * plane + o] = b2;
    }
}

// ===================== argmax over P=256 per batch row =======================
__global__ void argmax_kernel(const float* __restrict__ mat,
                              const float* __restrict__ g,
                              const int* __restrict__ rowIdx, int useIdx,
                              int* __restrict__ out)
{
    int r = blockIdx.x;
    int t = threadIdx.x;
    int row = useIdx ? rowIdx[r] : r;
    float v = mat[row * PDIM + t] + g[(size_t)r * PDIM + t];

    __shared__ float sv[256];
    __shared__ int   si[256];
    sv[t] = v; si[t] = t;
    __syncthreads();
#pragma unroll
    for (int s = 128; s > 0; s >>= 1) {
        if (t < s) {
            float v2 = sv[t + s]; int i2 = si[t + s];
            if (v2 > sv[t] || (v2 == sv[t] && i2 < si[t])) { sv[t] = v2; si[t] = i2; }
        }
        __syncthreads();
    }
    if (t == 0) out[r] = si[0];
}

// ===================== pairwise squared-distance tables ======================
__global__ void dist_kernel(const float* __restrict__ A, int lda, int aoff,
                            const float* __restrict__ Bm, int ldb,
                            float* __restrict__ D)
{
    __shared__ float As[16][33];
    __shared__ float Bs[16][33];
    int tx = threadIdx.x % 16;
    int ty = threadIdx.x / 16;
    int p0 = blockIdx.y * 16, q0 = blockIdx.x * 16;
    float acc = 0.0f;

    for (int k0 = 0; k0 < 2048; k0 += 32) {
        int row = threadIdx.x / 16;
        int col = (threadIdx.x % 16) * 2;
        float2 va = *reinterpret_cast<const float2*>(&A[(size_t)(p0 + row) * lda + aoff + k0 + col]);
        As[row][col] = va.x; As[row][col + 1] = va.y;
        float2 vb = *reinterpret_cast<const float2*>(&Bm[(size_t)(q0 + row) * ldb + k0 + col]);
        Bs[row][col] = vb.x; Bs[row][col + 1] = vb.y;
        __syncthreads();
#pragma unroll
        for (int k = 0; k < 32; k++) {
            float d = As[ty][k] - Bs[tx][k];
            acc = fmaf(d, d, acc);
        }
        __syncthreads();
    }
    D[(p0 + ty) * PDIM + q0 + tx] = acc;
}

// ===================== scalar chain ==========================================
__global__ void pe_kernel()
{
    int b = blockIdx.x * blockDim.x + threadIdx.x;
    int i0 = d_i0[b], ni0 = d_ni0[b], ni1 = d_ni1[b];
    d_pe[b] = (d_D0[i0 * PDIM + ni0] + d_D1[i0 * PDIM + ni1]) * (1.0f / 4096.0f);
}
__global__ void mean_kernel()
{
    __shared__ float s[1024];
    int t = threadIdx.x;
    float v = 0.0f;
    for (int i = t; i < BSZ; i += 1024) v += d_pe[i];
    s[t] = v; __syncthreads();
    for (int st = 512; st > 0; st >>= 1) { if (t < st) s[t] += s[t + st]; __syncthreads(); }
    if (t == 0) d_scal[0] = s[0] * (1.0f / 4096.0f);
}
__global__ void conf_kernel()
{
    int b = blockIdx.x * blockDim.x + threadIdx.x;
    float pe   = d_pe[b];
    float pc   = fabsf(pe - d_scal[0]);
    float temp = 1.0f / (1.0f + expf(-pc));
    float conf = 0.5f * (tanhf(-pe * temp) + 1.0f);
    d_conf[b] = conf;
    d_prod[b] = conf * (1.0f - conf);
}
__global__ void rc_kernel()
{
    __shared__ float s[1024];
    int t = threadIdx.x;
    float v = 0.0f;
    for (int i = t; i < BSZ; i += 1024) v += d_prod[i];
    s[t] = v; __syncthreads();
    for (int st = 512; st > 0; st >>= 1) { if (t < st) s[t] += s[t + st]; __syncthreads(); }
    if (t == 0) d_scal[1] = 0.1f * (s[0] * (1.0f / 4096.0f));
}

// ===================== output kernels ========================================
__global__ void contup_kernel(float* __restrict__ out)
{
    int i = blockIdx.x * blockDim.x + threadIdx.x;
    float4 h = reinterpret_cast<const float4*>(d_hidden)[i];
    float s = 1.0f - d_conf[i >> 10];
    h.x *= s; h.y *= s; h.z *= s; h.w *= s;
    reinterpret_cast<float4*>(out)[i] = h;
}
__global__ void penult_kernel(float* __restrict__ out)
{
    int i = blockIdx.x * blockDim.x + threadIdx.x;
    int b = i >> 9;
    int j = i & 511;
    float4 p0 = reinterpret_cast<const float4*>(d_PEN0)[d_i0[b] * 512 + j];
    float4 p1 = reinterpret_cast<const float4*>(d_PEN1)[d_i1[b] * 512 + j];
    float c = d_conf[b];
    float4 o;
    o.x = (p0.x + p1.x) * c;
    o.y = (p0.y + p1.y) * c;
    o.z = (p0.z + p1.z) * c;
    o.w = (p0.w + p1.w) * c;
    reinterpret_cast<float4*>(out)[i] = o;
}
__global__ void peout_kernel(float* __restrict__ out)
{
    int b = blockIdx.x * blockDim.x + threadIdx.x;
    out[b] = d_pe[b] + d_scal[1];
}

// ===================== launch ================================================
static inline void launch_gemm(int EPI, int M, int N, int K,
                               const float* A, int lda,
                               const __nv_bfloat16* Bt, int ldb, size_t planeB,
                               const float* bias, float* C, int ldc)
{
    dim3 grid((M >> 7) * (N >> 7));
    if (EPI == 0)      mma_gemm<0><<<grid, 256, SMEM_GEMM>>>(M, N, K, A, lda, Bt, ldb, planeB, bias, C, ldc);
    else if (EPI == 1) mma_gemm<1><<<grid, 256, SMEM_GEMM>>>(M, N, K, A, lda, Bt, ldb, planeB, bias, C, ldc);
    else               mma_gemm<2><<<grid, 256, SMEM_GEMM>>>(M, N, K, A, lda, Bt, ldb, planeB, bias, C, ldc);
}

extern "C" void kernel_launch(void* const* d_in, const int* in_sizes, int n_in,
                              void* d_out, int out_size)
{
    const float* x         = (const float*)d_in[0];
    const float* g_main0   = (const float*)d_in[1];
    const float* g_main1   = (const float*)d_in[2];
    const float* g_next0   = (const float*)d_in[3];
    const float* g_next1   = (const float*)d_in[4];
    const float* W_proc    = (const float*)d_in[5];
    const float* b_proc    = (const float*)d_in[6];
    const float* patterns0 = (const float*)d_in[7];
    const float* patterns1 = (const float*)d_in[8];
    const float* attn0_W   = (const float*)d_in[9];
    const float* attn0_b   = (const float*)d_in[10];
    const float* attn1_W   = (const float*)d_in[11];
    const float* attn1_b   = (const float*)d_in[12];
    const float* proj0_W   = (const float*)d_in[13];
    const float* proj0_b   = (const float*)d_in[14];
    const float* pen_W     = (const float*)d_in[15];
    const float* pen_b     = (const float*)d_in[16];
    const float* nW_proc   = (const float*)d_in[17];
    const float* nb_proc   = (const float*)d_in[18];
    const float* npat0     = (const float*)d_in[19];
    const float* npat1     = (const float*)d_in[20];
    const float* nattn0_W  = (const float*)d_in[21];
    const float* nattn0_b  = (const float*)d_in[22];
    const float* nattn1_W  = (const float*)d_in[23];
    const float* nattn1_b  = (const float*)d_in[24];

    static int smem_set = 0;
    if (!smem_set) {
        cudaFuncSetAttribute(mma_gemm<0>, cudaFuncAttributeMaxDynamicSharedMemorySize, SMEM_GEMM);
        cudaFuncSetAttribute(mma_gemm<1>, cudaFuncAttributeMaxDynamicSharedMemorySize, SMEM_GEMM);
        cudaFuncSetAttribute(mma_gemm<2>, cudaFuncAttributeMaxDynamicSharedMemorySize, SMEM_GEMM);
        smem_set = 1;
    }

    float *hidden, *act, *logit, *Mcur, *L1mat, *NL1, *PEN0, *PEN1, *D0, *D1;
    int *i0p, *i1p, *ni0p, *ni1p;
    __nv_bfloat16 *wproc, *nwproc, *a0w, *na0w, *p0w, *a1w, *na1w, *penw;
    cudaGetSymbolAddress((void**)&hidden, d_hidden);
    cudaGetSymbolAddress((void**)&act,    d_act);
    cudaGetSymbolAddress((void**)&logit,  d_logit);
    cudaGetSymbolAddress((void**)&Mcur,   d_Mcur);
    cudaGetSymbolAddress((void**)&L1mat,  d_L1mat);
    cudaGetSymbolAddress((void**)&NL1,    d_NL1);
    cudaGetSymbolAddress((void**)&PEN0,   d_PEN0);
    cudaGetSymbolAddress((void**)&PEN1,   d_PEN1);
    cudaGetSymbolAddress((void**)&D0,     d_D0);
    cudaGetSymbolAddress((void**)&D1,     d_D1);
    cudaGetSymbolAddress((void**)&i0p,    d_i0);
    cudaGetSymbolAddress((void**)&i1p,    d_i1);
    cudaGetSymbolAddress((void**)&ni0p,   d_ni0);
    cudaGetSymbolAddress((void**)&ni1p,   d_ni1);
    cudaGetSymbolAddress((void**)&wproc,  bt_wproc);
    cudaGetSymbolAddress((void**)&nwproc, bt_nwproc);
    cudaGetSymbolAddress((void**)&a0w,    bt_attn0);
    cudaGetSymbolAddress((void**)&na0w,   bt_nattn0);
    cudaGetSymbolAddress((void**)&p0w,    bt_proj0);
    cudaGetSymbolAddress((void**)&a1w,    bt_attn1);
    cudaGetSymbolAddress((void**)&na1w,   bt_nattn1);
    cudaGetSymbolAddress((void**)&penw,   bt_pen);

    float* out = (float*)d_out;
    float* out_cont = out;
    float* out_pen  = out + (size_t)BSZ * HDIM;
    float* out_pe   = out + (size_t)BSZ * HDIM + (size_t)BSZ * PENDIM;

    // ---- transpose + split all B operands ----
    tsplit_kernel<<<dim3(HDIM/32, DIN/32),   256>>>(W_proc,   DIN,        HDIM,  wproc,  (size_t)HDIM  * DIN);
    tsplit_kernel<<<dim3(HDIM/32, HDIM/32),  256>>>(nW_proc,  HDIM,       HDIM,  nwproc, (size_t)HDIM  * HDIM);
    tsplit_kernel<<<dim3(PDIM/32, HDIM/32),  256>>>(attn0_W,  HDIM,       PDIM,  a0w,    (size_t)PDIM  * HDIM);
    tsplit_kernel<<<dim3(PDIM/32, HDIM/32),  256>>>(nattn0_W, HDIM,       PDIM,  na0w,   (size_t)PDIM  * HDIM);
    tsplit_kernel<<<dim3(L1DIM/32, HDIM/32), 256>>>(proj0_W,  HDIM,       L1DIM, p0w,    (size_t)L1DIM * HDIM);
    tsplit_kernel<<<dim3(PDIM/32, L1DIM/32), 256>>>(attn1_W,  L1DIM,      PDIM,  a1w,    (size_t)PDIM  * L1DIM);
    tsplit_kernel<<<dim3(PDIM/32, L1DIM/32), 256>>>(nattn1_W, L1DIM,      PDIM,  na1w,   (size_t)PDIM  * L1DIM);
    tsplit_kernel<<<dim3(PENDIM/32, (HDIM+L1DIM)/32), 256>>>(pen_W, HDIM + L1DIM, PENDIM, penw, (size_t)PENDIM * (HDIM + L1DIM));

    // ---- pairwise distance tables (SIMT, tiny) ----
    dist_kernel<<<dim3(16,16), 256>>>(patterns0, HDIM, 0,    npat0, L1DIM, D0);
    dist_kernel<<<dim3(16,16), 256>>>(patterns0, HDIM, 2048, npat1, L1DIM, D1);

    // ---- pattern-space precompute GEMMs ----
    launch_gemm(1, PDIM, L1DIM, HDIM, patterns0, HDIM, p0w, HDIM, (size_t)L1DIM * HDIM, proj0_b, Mcur, L1DIM);
    launch_gemm(1, PDIM, PDIM, L1DIM, Mcur, L1DIM, a1w, L1DIM, (size_t)PDIM * L1DIM, attn1_b, L1mat, PDIM);
    launch_gemm(1, PDIM, PDIM, L1DIM, npat0, L1DIM, na1w, L1DIM, (size_t)PDIM * L1DIM, nattn1_b, NL1, PDIM);
    launch_gemm(0, PDIM, PENDIM, HDIM, patterns0, HDIM, penw, HDIM + L1DIM, (size_t)PENDIM * (HDIM + L1DIM), (const float*)0, PEN0, PENDIM);
    launch_gemm(1, PDIM, PENDIM, L1DIM, patterns1, L1DIM, penw + HDIM, HDIM + L1DIM, (size_t)PENDIM * (HDIM + L1DIM), pen_b, PEN1, PENDIM);

    // ---- batch GEMM chain ----
    launch_gemm(2, BSZ, HDIM, DIN, x, DIN, wproc, DIN, (size_t)HDIM * DIN, b_proc, hidden, HDIM);
    launch_gemm(1, BSZ, PDIM, HDIM, hidden, HDIM, a0w, HDIM, (size_t)PDIM * HDIM, attn0_b, logit, PDIM);
    argmax_kernel<<<BSZ, 256>>>(logit, g_main0, (const int*)0, 0, i0p);

    launch_gemm(2, BSZ, HDIM, HDIM, hidden, HDIM, nwproc, HDIM, (size_t)HDIM * HDIM, nb_proc, act, HDIM);
    launch_gemm(1, BSZ, PDIM, HDIM, act, HDIM, na0w, HDIM, (size_t)PDIM * HDIM, nattn0_b, logit, PDIM);
    argmax_kernel<<<BSZ, 256>>>(logit, g_next0, (const int*)0, 0, ni0p);

    argmax_kernel<<<BSZ, 256>>>(L1mat, g_main1, i0p, 1, i1p);
    argmax_kernel<<<BSZ, 256>>>(NL1,   g_next1, ni0p, 1, ni1p);

    // ---- scalar chain ----
    pe_kernel  <<<BSZ/256, 256>>>();
    mean_kernel<<<1, 1024>>>();
    conf_kernel<<<BSZ/256, 256>>>();
    rc_kernel  <<<1, 1024>>>();

    // ---- outputs ----
    contup_kernel<<<(BSZ*HDIM/4)/256, 256>>>(out_cont);
    penult_kernel<<<(BSZ*PENDIM/4)/256, 256>>>(out_pen);
    peout_kernel <<<BSZ/256, 256>>>(out_pe);

    (void)in_sizes; (void)n_in; (void)out_size;
}